// round 5
// baseline (speedup 1.0000x reference)
#include <cuda_runtime.h>
#include <cstdint>

// ---------------------------------------------------------------------------
// Problem constants
// ---------------------------------------------------------------------------
// x: [1, 128, 224, 224]; C=128, H=W=224
// Block stage: 32x32 windows of 7x7 -> [1024, 49, 128]
// Grid stage : 7x7 windows of 32x32 -> [49, 1024, 128]
// Both stages: M = 50176 rows, D = 128, heads = 4, hd = 32, E = 512
static const int M_ROWS = 50176;
static const float SCALE = 5.656854249492381f;  // sqrt(32)  (reference MULTIPLIES)

// ---------------------------------------------------------------------------
// Scratch (device globals; no runtime allocation allowed)
// ---------------------------------------------------------------------------
__device__ float g_X  [6422528];    // stage input  [M,128]
__device__ float g_X2 [6422528];    // stage-2 input [M,128]
__device__ float g_QKV[19267584];   // [M,384]
__device__ float g_AO [6422528];    // attention out [M,128]
__device__ float g_P  [6422528];    // proj out     [M,128]
__device__ float g_Z  [6422528];    // post-LN      [M,128]
__device__ float g_H1 [25690112];   // fc1 out      [M,512]
__device__ float g_Y  [6422528];    // block output [M,128]

// ---------------------------------------------------------------------------
// Generic SGEMM: C[M,N] = A[M,K] * B[N,K]^T (+bias[N]) (+res[M,N])
// BM=BN=128, BK=16, 256 threads, 8x8 per thread.
// Requires M%128==0, N%128==0, K%16==0 (true for all call sites).
// ---------------------------------------------------------------------------
#define GBM 128
#define GBN 128
#define GBK 16

__global__ __launch_bounds__(256) void gemm_tn(
    const float* __restrict__ A, const float* __restrict__ B, float* __restrict__ C,
    int M, int N, int K,
    const float* __restrict__ bias, const float* __restrict__ res)
{
    __shared__ float As[GBK][GBM + 4];
    __shared__ float Bs[GBK][GBN + 4];

    const int tid = threadIdx.x;
    const int tx = tid & 15;          // 0..15 -> N direction
    const int ty = tid >> 4;          // 0..15 -> M direction
    const int row0 = blockIdx.x * GBM;
    const int col0 = blockIdx.y * GBN;

    float acc[8][8];
#pragma unroll
    for (int i = 0; i < 8; i++)
#pragma unroll
        for (int j = 0; j < 8; j++) acc[i][j] = 0.f;

    for (int k0 = 0; k0 < K; k0 += GBK) {
#pragma unroll
        for (int it = 0; it < 2; it++) {
            int a4 = tid + it * 256;          // 0..511
            int r  = a4 >> 2;                 // 0..127
            int kq = (a4 & 3) * 4;            // 0,4,8,12
            float4 va = *(const float4*)(A + (size_t)(row0 + r) * K + k0 + kq);
            As[kq + 0][r] = va.x; As[kq + 1][r] = va.y;
            As[kq + 2][r] = va.z; As[kq + 3][r] = va.w;
            float4 vb = *(const float4*)(B + (size_t)(col0 + r) * K + k0 + kq);
            Bs[kq + 0][r] = vb.x; Bs[kq + 1][r] = vb.y;
            Bs[kq + 2][r] = vb.z; Bs[kq + 3][r] = vb.w;
        }
        __syncthreads();

#pragma unroll
        for (int kk = 0; kk < GBK; kk++) {
            float ar[8], br[8];
#pragma unroll
            for (int u = 0; u < 8; u += 4)
                *(float4*)&ar[u] = *(const float4*)&As[kk][ty * 8 + u];
#pragma unroll
            for (int u = 0; u < 8; u += 4)
                *(float4*)&br[u] = *(const float4*)&Bs[kk][tx * 8 + u];
#pragma unroll
            for (int i = 0; i < 8; i++)
#pragma unroll
                for (int j = 0; j < 8; j++)
                    acc[i][j] += ar[i] * br[j];
        }
        __syncthreads();
    }

#pragma unroll
    for (int i = 0; i < 8; i++) {
        int r = row0 + ty * 8 + i;
#pragma unroll
        for (int j = 0; j < 8; j++) {
            int c = col0 + tx * 8 + j;
            float v = acc[i][j];
            if (bias) v += bias[c];
            if (res)  v += res[(size_t)r * N + c];
            C[(size_t)r * N + c] = v;
        }
    }
}

// ---------------------------------------------------------------------------
// window_partition (block stage): x[1,128,224,224] -> X[1024,49,128]
//   X[(hb*32+wb)][r*7+cc][ch] = x[ch][hb*7+r][wb*7+cc]
// ---------------------------------------------------------------------------
__global__ void part_block(const float* __restrict__ x, float* __restrict__ X)
{
    int e = blockIdx.x * 256 + threadIdx.x;          // 6422528 total, exact
    int ch  = e & 127;
    int t   = (e >> 7) % 49;
    int win = e / (49 * 128);
    int hb = win >> 5, wb = win & 31;
    int r = t / 7, cc = t % 7;
    X[e] = __ldg(&x[ch * 50176 + (hb * 7 + r) * 224 + (wb * 7 + cc)]);
}

// ---------------------------------------------------------------------------
// Quirky unbind(block) -> CHW -> partition(grid), composed:
//   X2[(gi*7+gj)][rr*32+ccg][ch] = net_quirky[ch][gi*32+rr][gj*32+ccg]
// where net_quirky flat (i*28672 + j*128 + ch) maps back into Y via
// (c,hb,r,cc,wb) with strides (50176,1568,224,32,1).
// ---------------------------------------------------------------------------
__global__ void b2g(const float* __restrict__ Y, float* __restrict__ X2)
{
    int e = blockIdx.x * 256 + threadIdx.x;
    int ch  = e & 127;
    int tok = (e >> 7) & 1023;
    int win = e >> 17;                 // /131072
    int gi = win / 7, gj = win % 7;
    int rr = tok >> 5, ccg = tok & 31;
    int i = gi * 32 + rr, j = gj * 32 + ccg;
    int flat = i * 28672 + j * 128 + ch;
    int c  = flat / 50176, r1 = flat % 50176;
    int hb = r1 / 1568,    r2 = r1 % 1568;
    int r  = r2 / 224,     r3 = r2 % 224;
    int cc = r3 >> 5,      wb = r3 & 31;
    X2[e] = __ldg(&Y[((hb * 32 + wb) * 49 + r * 7 + cc) * 128 + c]);
}

// ---------------------------------------------------------------------------
// Final: quirky unbind(grid) -> out[1,128,224,224]
// net_quirky flat (i*28672 + j*128 + c') maps into Yg via
// (c,gi,rr,ccg,gj) with strides (50176,7168,224,7,1).
// ---------------------------------------------------------------------------
__global__ void finalize_out(const float* __restrict__ Y, float* __restrict__ out)
{
    int e = blockIdx.x * 256 + threadIdx.x;          // e = cp*50176 + i*224 + j
    int cp = e / 50176, rem = e % 50176;
    int i = rem / 224, j = rem % 224;
    int flat = i * 28672 + j * 128 + cp;
    int c   = flat / 50176, r1 = flat % 50176;
    int gi  = r1 / 7168,    r2 = r1 % 7168;
    int rr  = r2 / 224,     r3 = r2 % 224;
    int ccg = r3 / 7,       gj = r3 % 7;
    out[e] = __ldg(&Y[((gi * 7 + gj) * 1024 + rr * 32 + ccg) * 128 + c]);
}

// ---------------------------------------------------------------------------
// Block attention: N=49, one block per (win, head); exact softmax per row.
// QKV row layout: [q(4*32) | k(4*32) | v(4*32)], head h at offset h*32.
// ---------------------------------------------------------------------------
__global__ __launch_bounds__(64) void attn_block(
    const float* __restrict__ QKV, float* __restrict__ AO,
    const float* __restrict__ tbl)
{
    const int head = blockIdx.x & 3;
    const int win  = blockIdx.x >> 2;
    __shared__ float Ks[49][32];
    __shared__ float Vs[49][32];
    __shared__ float Bs[169];
    const int tid = threadIdx.x;
    const float* base = QKV + (size_t)win * 49 * 384;

    for (int idx = tid; idx < 49 * 32; idx += 64) {
        int j = idx >> 5, d = idx & 31;
        Ks[j][d] = base[j * 384 + 128 + head * 32 + d];
        Vs[j][d] = base[j * 384 + 256 + head * 32 + d];
    }
    for (int idx = tid; idx < 169; idx += 64) Bs[idx] = tbl[idx * 4 + head];
    __syncthreads();

    if (tid < 49) {
        float q[32];
#pragma unroll
        for (int d = 0; d < 32; d++) q[d] = base[tid * 384 + head * 32 + d];
        const int r1 = tid / 7, c1 = tid % 7;

        float s[49];
        float mx = -1e30f;
#pragma unroll 7
        for (int j = 0; j < 49; j++) {
            float a = 0.f;
#pragma unroll
            for (int d = 0; d < 32; d++) a += q[d] * Ks[j][d];
            int r2 = j / 7, c2 = j % 7;
            float v = a * SCALE + Bs[(r1 - r2 + 6) * 13 + (c1 - c2 + 6)];
            s[j] = v;
            mx = fmaxf(mx, v);
        }
        float l = 0.f;
        for (int j = 0; j < 49; j++) { float p = __expf(s[j] - mx); s[j] = p; l += p; }
        float inv = 1.f / l;

        float o[32];
#pragma unroll
        for (int d = 0; d < 32; d++) o[d] = 0.f;
        for (int j = 0; j < 49; j++) {
            float p = s[j];
#pragma unroll
            for (int d = 0; d < 32; d++) o[d] += p * Vs[j][d];
        }
        float* outp = AO + ((size_t)win * 49 + tid) * 128 + head * 32;
#pragma unroll
        for (int d = 0; d < 32; d++) outp[d] = o[d] * inv;
    }
}

// ---------------------------------------------------------------------------
// Grid attention: N=1024, flash-style online softmax, 64-key tiles.
// grid = (196 win*head, 4 row-tiles), 256 threads = 256 query rows.
// Per-head bias table (63*63=3969 entries) staged in smem.
// ---------------------------------------------------------------------------
__global__ __launch_bounds__(256) void attn_grid(
    const float* __restrict__ QKV, float* __restrict__ AO,
    const float* __restrict__ tbl)
{
    const int head = blockIdx.x & 3;
    const int win  = blockIdx.x >> 2;
    __shared__ float Ks[64][32];
    __shared__ float Vs[64][32];
    __shared__ float Bs[3969];
    const int tid = threadIdx.x;
    const float* base = QKV + (size_t)win * 1024 * 384;

    for (int idx = tid; idx < 3969; idx += 256) Bs[idx] = tbl[idx * 4 + head];

    const int i = blockIdx.y * 256 + tid;
    float q[32];
#pragma unroll
    for (int d = 0; d < 32; d++) q[d] = base[(size_t)i * 384 + head * 32 + d];
    const int r1 = i >> 5, c1 = i & 31;

    float m = -1e30f, l = 0.f;
    float acc[32];
#pragma unroll
    for (int d = 0; d < 32; d++) acc[d] = 0.f;

    for (int t = 0; t < 16; t++) {
        __syncthreads();
        for (int idx = tid; idx < 64 * 32; idx += 256) {
            int j = idx >> 5, d = idx & 31;
            int jj = t * 64 + j;
            Ks[j][d] = base[(size_t)jj * 384 + 128 + head * 32 + d];
            Vs[j][d] = base[(size_t)jj * 384 + 256 + head * 32 + d];
        }
        __syncthreads();

#pragma unroll 4
        for (int j = 0; j < 64; j++) {
            float s = 0.f;
#pragma unroll
            for (int d = 0; d < 32; d++) s += q[d] * Ks[j][d];
            int jj = t * 64 + j;
            int r2 = jj >> 5, c2 = jj & 31;
            s = s * SCALE + Bs[(r1 - r2 + 31) * 63 + (c1 - c2 + 31)];
            if (s > m) {                       // rare after warm-up
                float cor = __expf(m - s);
                l *= cor;
#pragma unroll
                for (int d = 0; d < 32; d++) acc[d] *= cor;
                m = s;
            }
            float p = __expf(s - m);
            l += p;
#pragma unroll
            for (int d = 0; d < 32; d++) acc[d] += p * Vs[j][d];
        }
    }

    float inv = 1.f / l;
    float* outp = AO + ((size_t)win * 1024 + i) * 128 + head * 32;
#pragma unroll
    for (int d = 0; d < 32; d++) outp[d] = acc[d] * inv;
}

// ---------------------------------------------------------------------------
// Fused: Z = LayerNorm(P + proj_b + X) * g + b      (one block per row)
// ---------------------------------------------------------------------------
__global__ __launch_bounds__(128) void ln_fused(
    const float* __restrict__ P, const float* __restrict__ X,
    const float* __restrict__ pb, const float* __restrict__ g,
    const float* __restrict__ b, float* __restrict__ Z)
{
    const int row = blockIdx.x;
    const int c = threadIdx.x;
    float v = P[(size_t)row * 128 + c] + pb[c] + X[(size_t)row * 128 + c];

    float s = v, s2 = v * v;
#pragma unroll
    for (int o = 16; o > 0; o >>= 1) {
        s  += __shfl_xor_sync(0xffffffffu, s,  o);
        s2 += __shfl_xor_sync(0xffffffffu, s2, o);
    }
    __shared__ float red[8];
    int w = c >> 5;
    if ((c & 31) == 0) { red[w] = s; red[4 + w] = s2; }
    __syncthreads();
    s  = red[0] + red[1] + red[2] + red[3];
    s2 = red[4] + red[5] + red[6] + red[7];

    float mu  = s * (1.f / 128.f);
    float var = s2 * (1.f / 128.f) - mu * mu;
    float rs  = rsqrtf(var + 1e-5f);
    Z[(size_t)row * 128 + c] = (v - mu) * rs * g[c] + b[c];
}

// ---------------------------------------------------------------------------
// Launch
// ---------------------------------------------------------------------------
extern "C" void kernel_launch(void* const* d_in, const int* in_sizes, int n_in,
                              void* d_out, int out_size)
{
    const float* x       = (const float*)d_in[0];
    const float* b_rel   = (const float*)d_in[1];
    const float* b_qkvw  = (const float*)d_in[2];
    const float* b_projw = (const float*)d_in[3];
    const float* b_projb = (const float*)d_in[4];
    const float* b_lng   = (const float*)d_in[5];
    const float* b_lnb   = (const float*)d_in[6];
    const float* b_fc1w  = (const float*)d_in[7];
    const float* b_fc1b  = (const float*)d_in[8];
    const float* b_fc2w  = (const float*)d_in[9];
    const float* b_fc2b  = (const float*)d_in[10];
    const float* g_rel   = (const float*)d_in[11];
    const float* g_qkvw  = (const float*)d_in[12];
    const float* g_projw = (const float*)d_in[13];
    const float* g_projb = (const float*)d_in[14];
    const float* g_lng   = (const float*)d_in[15];
    const float* g_lnb   = (const float*)d_in[16];
    const float* g_fc1w  = (const float*)d_in[17];
    const float* g_fc1b  = (const float*)d_in[18];
    const float* g_fc2w  = (const float*)d_in[19];
    const float* g_fc2b  = (const float*)d_in[20];

    float *X, *X2, *QKV, *AO, *P, *Z, *H1, *Y;
    cudaGetSymbolAddress((void**)&X,   g_X);
    cudaGetSymbolAddress((void**)&X2,  g_X2);
    cudaGetSymbolAddress((void**)&QKV, g_QKV);
    cudaGetSymbolAddress((void**)&AO,  g_AO);
    cudaGetSymbolAddress((void**)&P,   g_P);
    cudaGetSymbolAddress((void**)&Z,   g_Z);
    cudaGetSymbolAddress((void**)&H1,  g_H1);
    cudaGetSymbolAddress((void**)&Y,   g_Y);

    const int M = M_ROWS;                 // 50176
    const int EL_BLOCKS = 25088;          // 6422528 / 256

    // ---- Block stage ----
    part_block<<<EL_BLOCKS, 256>>>(x, X);
    gemm_tn<<<dim3(392, 3), 256>>>(X, b_qkvw, QKV, M, 384, 128, nullptr, nullptr);
    attn_block<<<4096, 64>>>(QKV, AO, b_rel);
    gemm_tn<<<dim3(392, 1), 256>>>(AO, b_projw, P, M, 128, 128, nullptr, nullptr);
    ln_fused<<<M, 128>>>(P, X, b_projb, b_lng, b_lnb, Z);
    gemm_tn<<<dim3(392, 4), 256>>>(Z, b_fc1w, H1, M, 512, 128, b_fc1b, nullptr);
    gemm_tn<<<dim3(392, 1), 256>>>(H1, b_fc2w, Y, M, 128, 512, b_fc2b, Z);

    // ---- Layout shuffle block -> grid (faithful quirky reshape) ----
    b2g<<<EL_BLOCKS, 256>>>(Y, X2);

    // ---- Grid stage ----
    gemm_tn<<<dim3(392, 3), 256>>>(X2, g_qkvw, QKV, M, 384, 128, nullptr, nullptr);
    attn_grid<<<dim3(196, 4), 256>>>(QKV, AO, g_rel);
    gemm_tn<<<dim3(392, 1), 256>>>(AO, g_projw, P, M, 128, 128, nullptr, nullptr);
    ln_fused<<<M, 128>>>(P, X2, g_projb, g_lng, g_lnb, Z);
    gemm_tn<<<dim3(392, 4), 256>>>(Z, g_fc1w, H1, M, 512, 128, g_fc1b, nullptr);
    gemm_tn<<<dim3(392, 1), 256>>>(H1, g_fc2w, Y, M, 128, 512, g_fc2b, Z);

    // ---- Final quirky unbind -> [1,128,224,224] ----
    finalize_out<<<EL_BLOCKS, 256>>>(Y, (float*)d_out);
}